// round 15
// baseline (speedup 1.0000x reference)
#include <cuda_runtime.h>
#include <cuda_fp16.h>
#include <math.h>
#include <stdint.h>

// Problem dims
#define T_DIM 4096
#define B_DIM 16
#define H_DIM 256
#define D_DIM 256
#define M_DIM (T_DIM * B_DIM)        // 65536
#define N1 (2 * H_DIM)               // 512
#define NCHUNK 64
#define LCH (T_DIM / NCHUNK)         // 64 timesteps per chunk
#define WARM 16                      // |Lam|<=e^-1 => trunc err <= 0.368^16 ~ 1.1e-7
#define CSH (NCHUNK * B_DIM * 64)    // threads per scan half (64 h-pairs): 65536

// -------- device scratch --------
__device__ __half g_Bu[(size_t)M_DIM * N1];      // Bu fp16 (GEMM1 out, scan in)
__device__ __half g_A1[(size_t)M_DIM * 256];     // x fp16
__device__ __half g_B1[512 * 256];               // gamma-scaled B fp16
__device__ __half g_A3[(size_t)M_DIM * 512];     // [h_re | h_im] fp16
__device__ __half g_B3[256 * 512];               // [C_re | -C_im] fp16
__device__ float g_lam[2 * H_DIM];
__device__ unsigned char g_flags[M_DIM];
__device__ int g_mode;

// ================= helpers =================
__device__ __forceinline__ uint32_t smem_u32(const void* p) {
    uint32_t a;
    asm("{ .reg .u64 t; cvta.to.shared.u64 t, %1; cvt.u32.u64 %0, t; }" : "=r"(a) : "l"(p));
    return a;
}
#define SWZ128(o) ((o) ^ (((o) >> 3) & 0x70))

#define CP_ASYNC16(dst, src) asm volatile("cp.async.cg.shared.global [%0], [%1], 16;" :: "r"(dst), "l"(src))
#define CP_COMMIT()          asm volatile("cp.async.commit_group;")

__device__ __forceinline__ void ldsm4(uint32_t& r0, uint32_t& r1, uint32_t& r2, uint32_t& r3, uint32_t a) {
    asm volatile("ldmatrix.sync.aligned.m8n8.x4.shared.b16 {%0,%1,%2,%3}, [%4];"
                 : "=r"(r0), "=r"(r1), "=r"(r2), "=r"(r3) : "r"(a));
}

__device__ __forceinline__ void mma_f16(float* d, const uint32_t* a, const uint32_t* b) {
    asm volatile(
        "mma.sync.aligned.m16n8k16.row.col.f32.f16.f16.f32 "
        "{%0,%1,%2,%3}, {%4,%5,%6,%7}, {%8,%9}, {%0,%1,%2,%3};"
        : "+f"(d[0]), "+f"(d[1]), "+f"(d[2]), "+f"(d[3])
        : "r"(a[0]), "r"(a[1]), "r"(a[2]), "r"(a[3]), "r"(b[0]), "r"(b[1]));
}

// ================= prep kernels =================
__global__ void k_detect(const unsigned char* __restrict__ s, int nbytes) {
    __shared__ int sh_gt1, sh_nm4;
    if (threadIdx.x == 0) { sh_gt1 = 0; sh_nm4 = 0; }
    __syncthreads();
    int gt1 = 0, nm4 = 0;
    for (int i = threadIdx.x; i < nbytes; i += blockDim.x) {
        unsigned char v = s[i];
        if (v > 1) gt1 = 1;
        if (v != 0 && (i & 3) != 0) nm4 = 1;
    }
    if (gt1) atomicOr(&sh_gt1, 1);
    if (nm4) atomicOr(&sh_nm4, 1);
    __syncthreads();
    if (threadIdx.x == 0) g_mode = sh_gt1 ? 2 : (sh_nm4 ? 0 : 1);
}

__global__ void k_flags(const void* __restrict__ s) {
    int i = blockIdx.x * blockDim.x + threadIdx.x;
    if (i >= M_DIM) return;
    int m = g_mode;
    unsigned char f;
    if (m == 0)       f = ((const unsigned char*)s)[i] != 0;
    else if (m == 1)  f = ((const int*)s)[i] != 0;
    else              f = ((const float*)s)[i] != 0.0f;
    g_flags[i] = f;
}

// merged: lam table + gamma*B -> g_B1 + [C_re|-C_im] -> g_B3
__global__ void k_prep(const float* __restrict__ nu_log, const float* __restrict__ theta_log,
                       const float* __restrict__ B_re, const float* __restrict__ B_im,
                       const float* __restrict__ C_re, const float* __restrict__ C_im) {
    int i = blockIdx.x * blockDim.x + threadIdx.x;
    if (i >= 512 * 256) return;
    int n = i >> 8, d = i & 255;
    int h = n & 255;
    float mag = expf(-expf(nu_log[h]));
    float gamma = sqrtf(fmaxf(1.0f - mag * mag, 1e-8f));
    float w = ((n < 256) ? B_re[h * 256 + d] : B_im[h * 256 + d]) * gamma;
    g_B1[i] = __float2half_rn(w);
    int d3 = i >> 9, k = i & 511;
    float c = (k < 256) ? C_re[d3 * 256 + k] : -C_im[d3 * 256 + (k - 256)];
    g_B3[i] = __float2half_rn(c);
    if (i < 256) {
        float th = expf(theta_log[i]);
        float mg = expf(-expf(nu_log[i]));
        g_lam[i] = mg * cosf(th);
        g_lam[256 + i] = mg * sinf(th);
    }
}

__global__ void k_xh(const float* __restrict__ x) {
    int i = blockIdx.x * blockDim.x + threadIdx.x;  // M*256 / 4
    if (i >= M_DIM * 64) return;
    float4 v = ((const float4*)x)[i];
    __half2 a = __floats2half2_rn(v.x, v.y);
    __half2 b = __floats2half2_rn(v.z, v.w);
    ((uint2*)g_A1)[i] = make_uint2(*(uint32_t*)&a, *(uint32_t*)&b);
}

// stage loader (256-thread CTA, half a 128B row per thread); kcg = global chunk
#define LOAD_STAGE_B(Abase, lda, Bbase, ldb, kcg, s, wrapv) do {                       \
    int _acol = (((kcg) < (wrapv)) ? (kcg) : (kcg) - (wrapv)) * 128;                   \
    int _bcol = (kcg) * 128;                                                           \
    uint32_t _sA = sb + (s) * 32768;                                                   \
    uint32_t _sB = _sA + 16384;                                                        \
    const char* _srcA = (const char*)(Abase) + (size_t)lrow * (lda) + _acol + lseg;    \
    const char* _srcB = (const char*)(Bbase) + (size_t)lrow * (ldb) + _bcol + lseg;    \
    _Pragma("unroll")                                                                  \
    for (int _j = 0; _j < 4; _j++) {                                                   \
        uint32_t _off = (uint32_t)lrow * 128 + lseg + _j * 16;                         \
        uint32_t _swo = SWZ128(_off);                                                  \
        CP_ASYNC16(_sA + _swo, (const void*)__cvta_generic_to_global(_srcA + _j * 16)); \
        CP_ASYNC16(_sB + _swo, (const void*)__cvta_generic_to_global(_srcB + _j * 16)); \
    } } while (0)

// ================= fp16 mma GEMM (templated, fully unrolled) =================
// CTA 128x128, 256 threads, 8 warps (2m x 4n), warp tile 64x32, BK=64, 3-stage.
// tn = tn_base + blockIdx.x * tn_stride (column split).
// KMAP=1: chunk kc -> (kc&1) + ((kc>>1)<<2) + 2*khalf  (h-half K-split for GEMM3).
// OUTH=1: fp16 out. OUTH=0: fp32 out; ACCUM=0 -> write + D*x(fp16), ACCUM=1 -> out += acc.
#define GSMEM (3 * 32768)

template <int OUTH, int NC, int WRAP, int KMAP, int ACCUM>
__global__ void __launch_bounds__(256, 2) mma_gemm(
    const __half* __restrict__ gA, int lda,
    const __half* __restrict__ gB, int ldb,
    void* __restrict__ Cout, int ldc,
    const float* __restrict__ Dv, const __half* __restrict__ Xh,
    int tn_base, int tn_stride, int khalf)
{
    extern __shared__ char smem[];
    uint32_t sb = smem_u32(smem);
    int tid = threadIdx.x, lane = tid & 31, wid = tid >> 5;
    int warpm = wid & 1, warpn = wid >> 1;
    int bm = blockIdx.y;
    int tn = tn_base + blockIdx.x * tn_stride;

    const char* Abase = (const char*)(gA + (size_t)(bm * 128) * lda);
    const char* Bbase = (const char*)(gB + (size_t)(tn * 128) * ldb);
    int ldab = lda * 2, ldbb = ldb * 2;  // bytes

    float acc[4][4][4];
    #pragma unroll
    for (int i = 0; i < 4; i++)
        #pragma unroll
        for (int j = 0; j < 4; j++)
            #pragma unroll
            for (int q = 0; q < 4; q++) acc[i][j][q] = 0.0f;

    int lrow = tid >> 1;
    int lseg = (tid & 1) * 64;

    int arow = warpm * 64 + (lane & 15);
    int brow = warpn * 32 + (lane & 15);
    int koff = (lane >> 4) * 16;

    int kh2 = khalf * 2;
    #define KCG(kc) (KMAP ? (((kc) & 1) + (((kc) >> 1) << 2) + kh2) : (kc))

    LOAD_STAGE_B(Abase, ldab, Bbase, ldbb, KCG(0), 0, WRAP); CP_COMMIT();
    LOAD_STAGE_B(Abase, ldab, Bbase, ldbb, KCG(1), 1, WRAP); CP_COMMIT();
    asm volatile("cp.async.wait_group 1;" ::: "memory");
    __syncthreads();

    #pragma unroll
    for (int kc = 0; kc < NC; kc++) {
        const int s = kc % 3;
        if (kc + 2 < NC) {
            LOAD_STAGE_B(Abase, ldab, Bbase, ldbb, KCG(kc + 2), (kc + 2) % 3, WRAP);
        }
        CP_COMMIT();

        uint32_t sA = sb + s * 32768, sB = sA + 16384;
        #pragma unroll
        for (int ks = 0; ks < 4; ks++) {
            const int kb = ks * 32;
            uint32_t af[4][4], bf[4][2];
            #pragma unroll
            for (int mt = 0; mt < 4; mt++) {
                uint32_t addr = sA + SWZ128((uint32_t)(arow + mt * 16) * 128 + kb + koff);
                ldsm4(af[mt][0], af[mt][1], af[mt][2], af[mt][3], addr);
            }
            #pragma unroll
            for (int np = 0; np < 2; np++) {
                uint32_t addr = sB + SWZ128((uint32_t)(brow + np * 16) * 128 + kb + koff);
                uint32_t r0, r1, r2, r3;
                ldsm4(r0, r1, r2, r3, addr);
                bf[2 * np][0] = r0;     bf[2 * np][1] = r2;
                bf[2 * np + 1][0] = r1; bf[2 * np + 1][1] = r3;
            }
            #pragma unroll
            for (int mt = 0; mt < 4; mt++)
                #pragma unroll
                for (int nt = 0; nt < 4; nt++)
                    mma_f16(acc[mt][nt], af[mt], bf[nt]);
        }

        asm volatile("cp.async.wait_group 1;" ::: "memory");
        __syncthreads();
    }

    // -------- epilogue --------
    int m0 = bm * 128 + warpm * 64;
    int n0 = tn * 128 + warpn * 32;
    int rq = lane >> 2, cq = (lane & 3) * 2;
    #pragma unroll
    for (int mt = 0; mt < 4; mt++) {
        #pragma unroll
        for (int h = 0; h < 2; h++) {
            int r = m0 + mt * 16 + h * 8 + rq;
            if (OUTH) {
                __half* crow = (__half*)Cout + (size_t)r * ldc;
                #pragma unroll
                for (int nt = 0; nt < 4; nt++) {
                    int c = n0 + nt * 8 + cq;
                    __half2 hv = __floats2half2_rn(acc[mt][nt][h * 2 + 0],
                                                   acc[mt][nt][h * 2 + 1]);
                    *(__half2*)(crow + c) = hv;
                }
            } else if (ACCUM) {
                float* crow = (float*)Cout + (size_t)r * ldc;
                #pragma unroll
                for (int nt = 0; nt < 4; nt++) {
                    int c = n0 + nt * 8 + cq;
                    float2 prev = *(float2*)(crow + c);
                    *(float2*)(crow + c) = make_float2(prev.x + acc[mt][nt][h * 2 + 0],
                                                       prev.y + acc[mt][nt][h * 2 + 1]);
                }
            } else {
                float* crow = (float*)Cout + (size_t)r * ldc;
                const __half* xrow = Xh + (size_t)r * ldc;
                #pragma unroll
                for (int nt = 0; nt < 4; nt++) {
                    int c = n0 + nt * 8 + cq;
                    float2 xv = __half22float2(*(const __half2*)(xrow + c));
                    float v0 = fmaf(Dv[c],     xv.x, acc[mt][nt][h * 2 + 0]);
                    float v1 = fmaf(Dv[c + 1], xv.y, acc[mt][nt][h * 2 + 1]);
                    *(float2*)(crow + c) = make_float2(v0, v1);
                }
            }
        }
    }
}

// ================= windowed segmented scan (half2, h-half per launch) =================
__global__ void scan_win(const float* __restrict__ st_re, const float* __restrict__ st_im,
                         int h2_base) {
    int tg = blockIdx.x * blockDim.x + threadIdx.x;
    if (tg >= CSH) return;
    int hh = tg & 63;
    int b = (tg >> 6) & 15;
    int c = tg >> 10;
    int h = (h2_base + hh) * 2;

    float2 lr = *(const float2*)(g_lam + h);
    float2 li = *(const float2*)(g_lam + H_DIM + h);

    float sr0 = 0.0f, si0 = 0.0f, sr1 = 0.0f, si1 = 0.0f;
    int t0 = c * LCH;
    int tstart = t0 - WARM;
    if (c == 0) {
        sr0 = st_re[b * 256 + h];     sr1 = st_re[b * 256 + h + 1];
        si0 = st_im[b * 256 + h];     si1 = st_im[b * 256 + h + 1];
        tstart = 0;
    }
    for (int t = tstart; t < t0 + LCH; t++) {
        int row = t * B_DIM + b;
        const __half* p = g_Bu + (size_t)row * N1;
        float2 ur = __half22float2(*(const __half2*)(p + h));
        float2 ui = __half22float2(*(const __half2*)(p + H_DIM + h));
        if (g_flags[row]) {
            sr0 = ur.x; si0 = ui.x; sr1 = ur.y; si1 = ui.y;
        } else {
            float n0 = lr.x * sr0 - li.x * si0 + ur.x;
            si0 = lr.x * si0 + li.x * sr0 + ui.x; sr0 = n0;
            float n1 = lr.y * sr1 - li.y * si1 + ur.y;
            si1 = lr.y * si1 + li.y * sr1 + ui.y; sr1 = n1;
        }
        if (t >= t0) {
            __half* q = g_A3 + (size_t)row * 512;
            *(__half2*)(q + h)       = __floats2half2_rn(sr0, sr1);
            *(__half2*)(q + 256 + h) = __floats2half2_rn(si0, si1);
        }
    }
}

// ================= launch =================
extern "C" void kernel_launch(void* const* d_in, const int* in_sizes, int n_in,
                              void* d_out, int out_size) {
    const float* x        = (const float*)d_in[0];
    const void*  starts   = d_in[1];
    const float* state_re = (const float*)d_in[2];
    const float* state_im = (const float*)d_in[3];
    const float* nu_log   = (const float*)d_in[4];
    const float* theta_log= (const float*)d_in[5];
    const float* B_re     = (const float*)d_in[6];
    const float* B_im     = (const float*)d_in[7];
    const float* C_re     = (const float*)d_in[8];
    const float* C_im     = (const float*)d_in[9];
    const float* Dvec     = (const float*)d_in[10];
    float* out = (float*)d_out;

    __half *Bu_p, *A1_p, *A3_p, *B1_p, *B3_p;
    cudaGetSymbolAddress((void**)&Bu_p, g_Bu);
    cudaGetSymbolAddress((void**)&A1_p, g_A1);
    cudaGetSymbolAddress((void**)&A3_p, g_A3);
    cudaGetSymbolAddress((void**)&B1_p, g_B1);
    cudaGetSymbolAddress((void**)&B3_p, g_B3);

    cudaFuncSetAttribute((const void*)mma_gemm<1, 4, 4, 0, 0>,
                         cudaFuncAttributeMaxDynamicSharedMemorySize, GSMEM);
    cudaFuncSetAttribute((const void*)mma_gemm<0, 4, 8, 1, 0>,
                         cudaFuncAttributeMaxDynamicSharedMemorySize, GSMEM);
    cudaFuncSetAttribute((const void*)mma_gemm<0, 4, 8, 1, 1>,
                         cudaFuncAttributeMaxDynamicSharedMemorySize, GSMEM);

    // side stream + events, created ONCE on the first (uncaptured) call
    static cudaStream_t s2 = nullptr;
    static cudaEvent_t evF = nullptr, evFlags = nullptr, evScanB = nullptr;
    static int inited = 0;
    if (!inited) {
        inited = 1;
        if (cudaStreamCreateWithFlags(&s2, cudaStreamNonBlocking) != cudaSuccess) s2 = nullptr;
        if (s2) {
            if (cudaEventCreateWithFlags(&evF, cudaEventDisableTiming) != cudaSuccess ||
                cudaEventCreateWithFlags(&evFlags, cudaEventDisableTiming) != cudaSuccess ||
                cudaEventCreateWithFlags(&evScanB, cudaEventDisableTiming) != cudaSuccess) {
                s2 = nullptr;
            }
        }
    }

    dim3 gridG1h(2, M_DIM / 128);     // GEMM1 column half (2 of 4 tiles)
    dim3 gridG3(2, M_DIM / 128);      // GEMM3 (both column tiles), K-half per launch

    k_prep<<<512, 256>>>(nu_log, theta_log, B_re, B_im, C_re, C_im);
    k_xh<<<(M_DIM * 64) / 256, 256>>>(x);

    if (s2) {
        cudaEventRecord(evF, 0);
        cudaStreamWaitEvent(s2, evF, 0);
        // s2: detect -> flags -> G1b (h>=128) -> scan_b
        k_detect<<<1, 1024, 0, s2>>>((const unsigned char*)starts, M_DIM);
        k_flags<<<M_DIM / 256, 256, 0, s2>>>(starts);
        cudaEventRecord(evFlags, s2);
        mma_gemm<1, 4, 4, 0, 0><<<gridG1h, 256, GSMEM, s2>>>(A1_p, 256, B1_p, 256,
                                                             (void*)Bu_p, 512, nullptr, nullptr, 1, 2, 0);
        scan_win<<<CSH / 256, 256, 0, s2>>>(state_re, state_im, 64);
        cudaEventRecord(evScanB, s2);

        // main: G1a (h<128) -> scan_a -> G3a (K-half 0, write+D*x) -> G3b (K-half 1, accumulate)
        mma_gemm<1, 4, 4, 0, 0><<<gridG1h, 256, GSMEM>>>(A1_p, 256, B1_p, 256,
                                                         (void*)Bu_p, 512, nullptr, nullptr, 0, 2, 0);
        cudaStreamWaitEvent(0, evFlags, 0);
        scan_win<<<CSH / 256, 256>>>(state_re, state_im, 0);
        mma_gemm<0, 4, 8, 1, 0><<<gridG3, 256, GSMEM>>>(A3_p, 512, B3_p, 512,
                                                        (void*)out, 256, Dvec, A1_p, 0, 1, 0);
        cudaStreamWaitEvent(0, evScanB, 0);
        mma_gemm<0, 4, 8, 1, 1><<<gridG3, 256, GSMEM>>>(A3_p, 512, B3_p, 512,
                                                        (void*)out, 256, Dvec, A1_p, 0, 1, 1);
    } else {
        k_detect<<<1, 1024>>>((const unsigned char*)starts, M_DIM);
        k_flags<<<M_DIM / 256, 256>>>(starts);
        mma_gemm<1, 4, 4, 0, 0><<<gridG1h, 256, GSMEM>>>(A1_p, 256, B1_p, 256,
                                                         (void*)Bu_p, 512, nullptr, nullptr, 0, 2, 0);
        mma_gemm<1, 4, 4, 0, 0><<<gridG1h, 256, GSMEM>>>(A1_p, 256, B1_p, 256,
                                                         (void*)Bu_p, 512, nullptr, nullptr, 1, 2, 0);
        scan_win<<<CSH / 256, 256>>>(state_re, state_im, 0);
        scan_win<<<CSH / 256, 256>>>(state_re, state_im, 64);
        mma_gemm<0, 4, 8, 1, 0><<<gridG3, 256, GSMEM>>>(A3_p, 512, B3_p, 512,
                                                        (void*)out, 256, Dvec, A1_p, 0, 1, 0);
        mma_gemm<0, 4, 8, 1, 1><<<gridG3, 256, GSMEM>>>(A3_p, 512, B3_p, 512,
                                                        (void*)out, 256, Dvec, A1_p, 0, 1, 1);
    }
}

// round 16
// speedup vs baseline: 1.1257x; 1.1257x over previous
#include <cuda_runtime.h>
#include <cuda_fp16.h>
#include <math.h>
#include <stdint.h>

// Problem dims
#define T_DIM 4096
#define B_DIM 16
#define H_DIM 256
#define D_DIM 256
#define M_DIM (T_DIM * B_DIM)        // 65536
#define N1 (2 * H_DIM)               // 512
#define NCHUNK 64
#define LCH (T_DIM / NCHUNK)         // 64 timesteps per chunk
#define WARM 16                      // |Lam|<=e^-1 => trunc err <= 0.368^16 ~ 1.1e-7
#define CSH (NCHUNK * B_DIM * 64)    // threads per scan half (64 h-pairs): 65536

// -------- device scratch --------
__device__ __half g_Bu[(size_t)M_DIM * N1];      // Bu fp16 (GEMM1 out, scan in)
__device__ __half g_A1[(size_t)M_DIM * 256];     // x fp16
__device__ __half g_B1[512 * 256];               // gamma-scaled B fp16
__device__ __half g_A3[(size_t)M_DIM * 512];     // [h_re | h_im] fp16
__device__ __half g_B3[256 * 512];               // [C_re | -C_im] fp16
__device__ float g_lam[2 * H_DIM];
__device__ unsigned char g_flags[M_DIM];
__device__ int g_mode;

// ================= helpers =================
__device__ __forceinline__ uint32_t smem_u32(const void* p) {
    uint32_t a;
    asm("{ .reg .u64 t; cvta.to.shared.u64 t, %1; cvt.u32.u64 %0, t; }" : "=r"(a) : "l"(p));
    return a;
}
#define SWZ128(o) ((o) ^ (((o) >> 3) & 0x70))

#define CP_ASYNC16(dst, src) asm volatile("cp.async.cg.shared.global [%0], [%1], 16;" :: "r"(dst), "l"(src))
#define CP_COMMIT()          asm volatile("cp.async.commit_group;")

__device__ __forceinline__ void ldsm4(uint32_t& r0, uint32_t& r1, uint32_t& r2, uint32_t& r3, uint32_t a) {
    asm volatile("ldmatrix.sync.aligned.m8n8.x4.shared.b16 {%0,%1,%2,%3}, [%4];"
                 : "=r"(r0), "=r"(r1), "=r"(r2), "=r"(r3) : "r"(a));
}

__device__ __forceinline__ void mma_f16(float* d, const uint32_t* a, const uint32_t* b) {
    asm volatile(
        "mma.sync.aligned.m16n8k16.row.col.f32.f16.f16.f32 "
        "{%0,%1,%2,%3}, {%4,%5,%6,%7}, {%8,%9}, {%0,%1,%2,%3};"
        : "+f"(d[0]), "+f"(d[1]), "+f"(d[2]), "+f"(d[3])
        : "r"(a[0]), "r"(a[1]), "r"(a[2]), "r"(a[3]), "r"(b[0]), "r"(b[1]));
}

// ================= prep kernels =================
__global__ void k_detect(const unsigned char* __restrict__ s, int nbytes) {
    __shared__ int sh_gt1, sh_nm4;
    if (threadIdx.x == 0) { sh_gt1 = 0; sh_nm4 = 0; }
    __syncthreads();
    int gt1 = 0, nm4 = 0;
    for (int i = threadIdx.x; i < nbytes; i += blockDim.x) {
        unsigned char v = s[i];
        if (v > 1) gt1 = 1;
        if (v != 0 && (i & 3) != 0) nm4 = 1;
    }
    if (gt1) atomicOr(&sh_gt1, 1);
    if (nm4) atomicOr(&sh_nm4, 1);
    __syncthreads();
    if (threadIdx.x == 0) g_mode = sh_gt1 ? 2 : (sh_nm4 ? 0 : 1);
}

__global__ void k_flags(const void* __restrict__ s) {
    int i = blockIdx.x * blockDim.x + threadIdx.x;
    if (i >= M_DIM) return;
    int m = g_mode;
    unsigned char f;
    if (m == 0)       f = ((const unsigned char*)s)[i] != 0;
    else if (m == 1)  f = ((const int*)s)[i] != 0;
    else              f = ((const float*)s)[i] != 0.0f;
    g_flags[i] = f;
}

// merged: lam table + gamma*B -> g_B1 + [C_re|-C_im] -> g_B3
__global__ void k_prep(const float* __restrict__ nu_log, const float* __restrict__ theta_log,
                       const float* __restrict__ B_re, const float* __restrict__ B_im,
                       const float* __restrict__ C_re, const float* __restrict__ C_im) {
    int i = blockIdx.x * blockDim.x + threadIdx.x;
    if (i >= 512 * 256) return;
    int n = i >> 8, d = i & 255;
    int h = n & 255;
    float mag = expf(-expf(nu_log[h]));
    float gamma = sqrtf(fmaxf(1.0f - mag * mag, 1e-8f));
    float w = ((n < 256) ? B_re[h * 256 + d] : B_im[h * 256 + d]) * gamma;
    g_B1[i] = __float2half_rn(w);
    int d3 = i >> 9, k = i & 511;
    float c = (k < 256) ? C_re[d3 * 256 + k] : -C_im[d3 * 256 + (k - 256)];
    g_B3[i] = __float2half_rn(c);
    if (i < 256) {
        float th = expf(theta_log[i]);
        float mg = expf(-expf(nu_log[i]));
        g_lam[i] = mg * cosf(th);
        g_lam[256 + i] = mg * sinf(th);
    }
}

__global__ void k_xh(const float* __restrict__ x) {
    int i = blockIdx.x * blockDim.x + threadIdx.x;  // M*256 / 4
    if (i >= M_DIM * 64) return;
    float4 v = ((const float4*)x)[i];
    __half2 a = __floats2half2_rn(v.x, v.y);
    __half2 b = __floats2half2_rn(v.z, v.w);
    ((uint2*)g_A1)[i] = make_uint2(*(uint32_t*)&a, *(uint32_t*)&b);
}

// stage loader (256-thread CTA, half a 128B row per thread)
#define LOAD_STAGE_B(Abase, lda, Bbase, ldb, kc, s, wrapv) do {                        \
    int _acol = (((kc) < (wrapv)) ? (kc) : (kc) - (wrapv)) * 128;                      \
    int _bcol = (kc) * 128;                                                            \
    uint32_t _sA = sb + (s) * 32768;                                                   \
    uint32_t _sB = _sA + 16384;                                                        \
    const char* _srcA = (const char*)(Abase) + (size_t)lrow * (lda) + _acol + lseg;    \
    const char* _srcB = (const char*)(Bbase) + (size_t)lrow * (ldb) + _bcol + lseg;    \
    _Pragma("unroll")                                                                  \
    for (int _j = 0; _j < 4; _j++) {                                                   \
        uint32_t _off = (uint32_t)lrow * 128 + lseg + _j * 16;                         \
        uint32_t _swo = SWZ128(_off);                                                  \
        CP_ASYNC16(_sA + _swo, (const void*)__cvta_generic_to_global(_srcA + _j * 16)); \
        CP_ASYNC16(_sB + _swo, (const void*)__cvta_generic_to_global(_srcB + _j * 16)); \
    } } while (0)

// ================= fp16 mma GEMM (templated, fully unrolled) =================
// CTA 128x128, 256 threads, 8 warps (2m x 4n), warp tile 64x32, BK=64, 3-stage.
// tn = tn_base + blockIdx.x * tn_stride (column split for GEMM1 halves).
// OUTH=1: fp16 out; OUTH=0: fp32 out + D*x(fp16).
#define GSMEM (3 * 32768)

template <int OUTH, int NC, int WRAP>
__global__ void __launch_bounds__(256, 2) mma_gemm(
    const __half* __restrict__ gA, int lda,
    const __half* __restrict__ gB, int ldb,
    void* __restrict__ Cout, int ldc,
    const float* __restrict__ Dv, const __half* __restrict__ Xh,
    int tn_base, int tn_stride)
{
    extern __shared__ char smem[];
    uint32_t sb = smem_u32(smem);
    int tid = threadIdx.x, lane = tid & 31, wid = tid >> 5;
    int warpm = wid & 1, warpn = wid >> 1;
    int bm = blockIdx.y;
    int tn = tn_base + blockIdx.x * tn_stride;

    const char* Abase = (const char*)(gA + (size_t)(bm * 128) * lda);
    const char* Bbase = (const char*)(gB + (size_t)(tn * 128) * ldb);
    int ldab = lda * 2, ldbb = ldb * 2;  // bytes

    float acc[4][4][4];
    #pragma unroll
    for (int i = 0; i < 4; i++)
        #pragma unroll
        for (int j = 0; j < 4; j++)
            #pragma unroll
            for (int q = 0; q < 4; q++) acc[i][j][q] = 0.0f;

    int lrow = tid >> 1;
    int lseg = (tid & 1) * 64;

    int arow = warpm * 64 + (lane & 15);
    int brow = warpn * 32 + (lane & 15);
    int koff = (lane >> 4) * 16;

    LOAD_STAGE_B(Abase, ldab, Bbase, ldbb, 0, 0, WRAP); CP_COMMIT();
    LOAD_STAGE_B(Abase, ldab, Bbase, ldbb, 1, 1, WRAP); CP_COMMIT();
    asm volatile("cp.async.wait_group 1;" ::: "memory");
    __syncthreads();

    #pragma unroll
    for (int kc = 0; kc < NC; kc++) {
        const int s = kc % 3;
        if (kc + 2 < NC) {
            LOAD_STAGE_B(Abase, ldab, Bbase, ldbb, kc + 2, (kc + 2) % 3, WRAP);
        }
        CP_COMMIT();

        uint32_t sA = sb + s * 32768, sB = sA + 16384;
        #pragma unroll
        for (int ks = 0; ks < 4; ks++) {
            const int kb = ks * 32;
            uint32_t af[4][4], bf[4][2];
            #pragma unroll
            for (int mt = 0; mt < 4; mt++) {
                uint32_t addr = sA + SWZ128((uint32_t)(arow + mt * 16) * 128 + kb + koff);
                ldsm4(af[mt][0], af[mt][1], af[mt][2], af[mt][3], addr);
            }
            #pragma unroll
            for (int np = 0; np < 2; np++) {
                uint32_t addr = sB + SWZ128((uint32_t)(brow + np * 16) * 128 + kb + koff);
                uint32_t r0, r1, r2, r3;
                ldsm4(r0, r1, r2, r3, addr);
                bf[2 * np][0] = r0;     bf[2 * np][1] = r2;
                bf[2 * np + 1][0] = r1; bf[2 * np + 1][1] = r3;
            }
            #pragma unroll
            for (int mt = 0; mt < 4; mt++)
                #pragma unroll
                for (int nt = 0; nt < 4; nt++)
                    mma_f16(acc[mt][nt], af[mt], bf[nt]);
        }

        asm volatile("cp.async.wait_group 1;" ::: "memory");
        __syncthreads();
    }

    // -------- epilogue --------
    int m0 = bm * 128 + warpm * 64;
    int n0 = tn * 128 + warpn * 32;
    int rq = lane >> 2, cq = (lane & 3) * 2;
    #pragma unroll
    for (int mt = 0; mt < 4; mt++) {
        #pragma unroll
        for (int h = 0; h < 2; h++) {
            int r = m0 + mt * 16 + h * 8 + rq;
            if (OUTH) {
                __half* crow = (__half*)Cout + (size_t)r * ldc;
                #pragma unroll
                for (int nt = 0; nt < 4; nt++) {
                    int c = n0 + nt * 8 + cq;
                    __half2 hv = __floats2half2_rn(acc[mt][nt][h * 2 + 0],
                                                   acc[mt][nt][h * 2 + 1]);
                    *(__half2*)(crow + c) = hv;
                }
            } else {
                float* crow = (float*)Cout + (size_t)r * ldc;
                const __half* xrow = Xh + (size_t)r * ldc;
                #pragma unroll
                for (int nt = 0; nt < 4; nt++) {
                    int c = n0 + nt * 8 + cq;
                    float2 xv = __half22float2(*(const __half2*)(xrow + c));
                    float v0 = fmaf(Dv[c],     xv.x, acc[mt][nt][h * 2 + 0]);
                    float v1 = fmaf(Dv[c + 1], xv.y, acc[mt][nt][h * 2 + 1]);
                    *(float2*)(crow + c) = make_float2(v0, v1);
                }
            }
        }
    }
}

// ================= windowed segmented scan (half2, h-half per launch) =================
__global__ void scan_win(const float* __restrict__ st_re, const float* __restrict__ st_im,
                         int h2_base) {
    int tg = blockIdx.x * blockDim.x + threadIdx.x;
    if (tg >= CSH) return;
    int hh = tg & 63;
    int b = (tg >> 6) & 15;
    int c = tg >> 10;
    int h = (h2_base + hh) * 2;

    float2 lr = *(const float2*)(g_lam + h);
    float2 li = *(const float2*)(g_lam + H_DIM + h);

    float sr0 = 0.0f, si0 = 0.0f, sr1 = 0.0f, si1 = 0.0f;
    int t0 = c * LCH;
    int tstart = t0 - WARM;
    if (c == 0) {
        sr0 = st_re[b * 256 + h];     sr1 = st_re[b * 256 + h + 1];
        si0 = st_im[b * 256 + h];     si1 = st_im[b * 256 + h + 1];
        tstart = 0;
    }
    for (int t = tstart; t < t0 + LCH; t++) {
        int row = t * B_DIM + b;
        const __half* p = g_Bu + (size_t)row * N1;
        float2 ur = __half22float2(*(const __half2*)(p + h));
        float2 ui = __half22float2(*(const __half2*)(p + H_DIM + h));
        if (g_flags[row]) {
            sr0 = ur.x; si0 = ui.x; sr1 = ur.y; si1 = ui.y;
        } else {
            float n0 = lr.x * sr0 - li.x * si0 + ur.x;
            si0 = lr.x * si0 + li.x * sr0 + ui.x; sr0 = n0;
            float n1 = lr.y * sr1 - li.y * si1 + ur.y;
            si1 = lr.y * si1 + li.y * sr1 + ui.y; sr1 = n1;
        }
        if (t >= t0) {
            __half* q = g_A3 + (size_t)row * 512;
            *(__half2*)(q + h)       = __floats2half2_rn(sr0, sr1);
            *(__half2*)(q + 256 + h) = __floats2half2_rn(si0, si1);
        }
    }
}

// ================= launch =================
extern "C" void kernel_launch(void* const* d_in, const int* in_sizes, int n_in,
                              void* d_out, int out_size) {
    const float* x        = (const float*)d_in[0];
    const void*  starts   = d_in[1];
    const float* state_re = (const float*)d_in[2];
    const float* state_im = (const float*)d_in[3];
    const float* nu_log   = (const float*)d_in[4];
    const float* theta_log= (const float*)d_in[5];
    const float* B_re     = (const float*)d_in[6];
    const float* B_im     = (const float*)d_in[7];
    const float* C_re     = (const float*)d_in[8];
    const float* C_im     = (const float*)d_in[9];
    const float* Dvec     = (const float*)d_in[10];
    float* out = (float*)d_out;

    __half *Bu_p, *A1_p, *A3_p, *B1_p, *B3_p;
    cudaGetSymbolAddress((void**)&Bu_p, g_Bu);
    cudaGetSymbolAddress((void**)&A1_p, g_A1);
    cudaGetSymbolAddress((void**)&A3_p, g_A3);
    cudaGetSymbolAddress((void**)&B1_p, g_B1);
    cudaGetSymbolAddress((void**)&B3_p, g_B3);

    cudaFuncSetAttribute((const void*)mma_gemm<1, 4, 4>,
                         cudaFuncAttributeMaxDynamicSharedMemorySize, GSMEM);
    cudaFuncSetAttribute((const void*)mma_gemm<0, 8, 8>,
                         cudaFuncAttributeMaxDynamicSharedMemorySize, GSMEM);

    // side stream + events, created ONCE on the first (uncaptured) call
    static cudaStream_t s2 = nullptr;
    static cudaEvent_t evF = nullptr, evX = nullptr, evPrep = nullptr,
                       evFlags = nullptr, evScanB = nullptr;
    static int inited = 0;
    if (!inited) {
        inited = 1;
        if (cudaStreamCreateWithFlags(&s2, cudaStreamNonBlocking) != cudaSuccess) s2 = nullptr;
        if (s2) {
            if (cudaEventCreateWithFlags(&evF, cudaEventDisableTiming) != cudaSuccess ||
                cudaEventCreateWithFlags(&evX, cudaEventDisableTiming) != cudaSuccess ||
                cudaEventCreateWithFlags(&evPrep, cudaEventDisableTiming) != cudaSuccess ||
                cudaEventCreateWithFlags(&evFlags, cudaEventDisableTiming) != cudaSuccess ||
                cudaEventCreateWithFlags(&evScanB, cudaEventDisableTiming) != cudaSuccess) {
                s2 = nullptr;
            }
        }
    }

    dim3 gridG1h(2, M_DIM / 128);     // GEMM1 column half (2 of 4 tiles)
    dim3 gridG3(2, M_DIM / 128);      // GEMM3 full K

    if (s2) {
        // fork: bring s2 into the capture graph with an empty dependency
        cudaEventRecord(evF, 0);
        cudaStreamWaitEvent(s2, evF, 0);

        // s2 head: prep (B1/B3/lam) -> detect -> flags
        k_prep<<<512, 256, 0, s2>>>(nu_log, theta_log, B_re, B_im, C_re, C_im);
        cudaEventRecord(evPrep, s2);
        k_detect<<<1, 1024, 0, s2>>>((const unsigned char*)starts, M_DIM);
        k_flags<<<M_DIM / 256, 256, 0, s2>>>(starts);
        cudaEventRecord(evFlags, s2);

        // main head: x -> fp16
        k_xh<<<(M_DIM * 64) / 256, 256>>>(x);
        cudaEventRecord(evX, 0);

        // main: G1a (h<128), needs prep
        cudaStreamWaitEvent(0, evPrep, 0);
        mma_gemm<1, 4, 4><<<gridG1h, 256, GSMEM>>>(A1_p, 256, B1_p, 256,
                                                   (void*)Bu_p, 512, nullptr, nullptr, 0, 2);
        // s2: G1b (h>=128), needs xh (prep already local) -> scan_b
        cudaStreamWaitEvent(s2, evX, 0);
        mma_gemm<1, 4, 4><<<gridG1h, 256, GSMEM, s2>>>(A1_p, 256, B1_p, 256,
                                                       (void*)Bu_p, 512, nullptr, nullptr, 1, 2);
        scan_win<<<CSH / 256, 256, 0, s2>>>(state_re, state_im, 64);
        cudaEventRecord(evScanB, s2);

        // main: scan_a (needs flags from s2), then GEMM3 (needs scan_b too)
        cudaStreamWaitEvent(0, evFlags, 0);
        scan_win<<<CSH / 256, 256>>>(state_re, state_im, 0);
        cudaStreamWaitEvent(0, evScanB, 0);
        mma_gemm<0, 8, 8><<<gridG3, 256, GSMEM>>>(A3_p, 512, B3_p, 512,
                                                  (void*)out, 256, Dvec, A1_p, 0, 1);
    } else {
        k_prep<<<512, 256>>>(nu_log, theta_log, B_re, B_im, C_re, C_im);
        k_xh<<<(M_DIM * 64) / 256, 256>>>(x);
        k_detect<<<1, 1024>>>((const unsigned char*)starts, M_DIM);
        k_flags<<<M_DIM / 256, 256>>>(starts);
        mma_gemm<1, 4, 4><<<gridG1h, 256, GSMEM>>>(A1_p, 256, B1_p, 256,
                                                   (void*)Bu_p, 512, nullptr, nullptr, 0, 2);
        mma_gemm<1, 4, 4><<<gridG1h, 256, GSMEM>>>(A1_p, 256, B1_p, 256,
                                                   (void*)Bu_p, 512, nullptr, nullptr, 1, 2);
        scan_win<<<CSH / 256, 256>>>(state_re, state_im, 0);
        scan_win<<<CSH / 256, 256>>>(state_re, state_im, 64);
        mma_gemm<0, 8, 8><<<gridG3, 256, GSMEM>>>(A3_p, 512, B3_p, 512,
                                                  (void*)out, 256, Dvec, A1_p, 0, 1);
    }
}